// round 3
// baseline (speedup 1.0000x reference)
#include <cuda_runtime.h>
#include <cstdint>

// inputs: (B=8, H=160, W=160, C=256) fp32 NHWC
// rois:   (N=1024, 5) fp32 [img_id, x0, y0, x1, y1]
// im_info:(N, 2) fp32 [H_img, W_img]
// output: (N, 7, 7, 256) fp32 = crop_and_resize(14x14 bilinear) -> maxpool 2x2 s2
//
// R3 strategy: process ROIs in image-id-sorted order so concurrently resident
// blocks share one ~13MB image in L2 (instead of thrashing all 8 = 105MB).

#define FEAT_H 160
#define FEAT_W 160
#define FEAT_C 256
#define CROP   14
#define POOL   7
#define NBATCH 8
#define MAXROI 4096

__device__ int g_order[MAXROI];

// ---- single-block binning kernel: sort roi indices by image id ----
__global__ void bin_rois_kernel(const float* __restrict__ rois, int n)
{
    __shared__ int s_cnt[NBATCH];
    __shared__ int s_off[NBATCH];
    __shared__ int s_cur[NBATCH];
    const int t = threadIdx.x;

    if (t < NBATCH) { s_cnt[t] = 0; }
    __syncthreads();

    int bin = -1;
    if (t < n) {
        bin = (int)rois[t * 5 + 0];
        bin = min(max(bin, 0), NBATCH - 1);
        atomicAdd(&s_cnt[bin], 1);
    }
    __syncthreads();

    if (t == 0) {
        int acc = 0;
        #pragma unroll
        for (int i = 0; i < NBATCH; ++i) { s_off[i] = acc; s_cur[i] = acc; acc += s_cnt[i]; }
    }
    __syncthreads();

    if (t < n) {
        int pos = atomicAdd(&s_cur[bin], 1);
        g_order[pos] = t;
    }
}

__device__ __forceinline__ void stcs_f2(float2* p, float2 v) {
    asm volatile("st.global.cs.v2.f32 [%0], {%1, %2};" :: "l"(p), "f"(v.x), "f"(v.y) : "memory");
}

__global__ __launch_bounds__(128)
void roipool_kernel(const float* __restrict__ in,
                    const float* __restrict__ rois,
                    const float* __restrict__ im_info,
                    float* __restrict__ out)
{
    const int blk  = blockIdx.x;           // sorted_roi * 49 + pooled_pixel
    const int sroi = blk / 49;
    const int pix  = blk - sroi * 49;
    const int roi  = g_order[sroi];        // image-sorted roi index
    const int py   = pix / POOL;
    const int px   = pix - py * POOL;
    const int t    = threadIdx.x;          // 0..127, float2 channel lane

    // --- ROI parameters (warp-uniform broadcast loads) ---
    const float b_f   = __ldg(&rois[roi * 5 + 0]);
    const float H_img = __ldg(&im_info[roi * 2 + 0]);
    const float W_img = __ldg(&im_info[roi * 2 + 1]);
    const float x1 = __ldg(&rois[roi * 5 + 1]) / W_img;
    const float y1 = __ldg(&rois[roi * 5 + 2]) / H_img;
    const float x2 = __ldg(&rois[roi * 5 + 3]) / W_img;
    const float y2 = __ldg(&rois[roi * 5 + 4]) / H_img;
    const int   b  = (int)b_f;

    // Reference arithmetic order: y1*(Hf-1) + iy * ((y2-y1)*(Hf-1)/(ch-1))
    const float Hm1 = (float)(FEAT_H - 1);
    const float Wm1 = (float)(FEAT_W - 1);
    const float sy = (y2 - y1) * Hm1 / (float)(CROP - 1);
    const float sx = (x2 - x1) * Wm1 / (float)(CROP - 1);
    const float by = y1 * Hm1;
    const float bx = x1 * Wm1;

    // --- coords for the 2x2 crop pixels feeding this pooled pixel ---
    float ylp[2], xlp[2];
    int   yl[2], yh[2], xl[2], xh[2];
    bool  vy[2], vx[2];

    #pragma unroll
    for (int i = 0; i < 2; ++i) {
        const float y = by + (float)(2 * py + i) * sy;
        vy[i]  = (y >= 0.0f) && (y <= Hm1);
        const float yf = floorf(y);
        ylp[i] = y - yf;
        yl[i]  = min(max((int)yf, 0), FEAT_H - 1);
        yh[i]  = min(max((int)yf + 1, 0), FEAT_H - 1);

        const float x = bx + (float)(2 * px + i) * sx;
        vx[i]  = (x >= 0.0f) && (x <= Wm1);
        const float xf = floorf(x);
        xlp[i] = x - xf;
        xl[i]  = min(max((int)xf, 0), FEAT_W - 1);
        xh[i]  = min(max((int)xf + 1, 0), FEAT_W - 1);
    }

    // --- batch ALL 16 tap loads (max MLP); 32-bit addressing throughout ---
    const float2* __restrict__ base = (const float2*)in + t;
    const int rb = b * (FEAT_H * FEAT_W);
    int off[16];
    #pragma unroll
    for (int iy = 0; iy < 2; ++iy) {
        const int rl = (rb + yl[iy] * FEAT_W) * (FEAT_C / 2);
        const int rh = (rb + yh[iy] * FEAT_W) * (FEAT_C / 2);
        #pragma unroll
        for (int ix = 0; ix < 2; ++ix) {
            const int k = (iy * 2 + ix) * 4;
            off[k + 0] = rl + xl[ix] * (FEAT_C / 2);
            off[k + 1] = rl + xh[ix] * (FEAT_C / 2);
            off[k + 2] = rh + xl[ix] * (FEAT_C / 2);
            off[k + 3] = rh + xh[ix] * (FEAT_C / 2);
        }
    }

    float2 v[16];
    #pragma unroll
    for (int k = 0; k < 16; ++k) v[k] = __ldg(base + off[k]);

    // --- bilinear + mask + running max ---
    const float NEG_INF = __int_as_float(0xff800000);
    float2 vmax = make_float2(NEG_INF, NEG_INF);

    #pragma unroll
    for (int iy = 0; iy < 2; ++iy) {
        #pragma unroll
        for (int ix = 0; ix < 2; ++ix) {
            const int k = (iy * 2 + ix) * 4;
            const float yw = ylp[iy];
            const float xw = xlp[ix];
            const bool  ok = vy[iy] && vx[ix];
            const float2 tl = v[k + 0], tr = v[k + 1], bl = v[k + 2], br = v[k + 3];
            float top, bot, r0, r1;
            top = tl.x + (tr.x - tl.x) * xw;  bot = bl.x + (br.x - bl.x) * xw;  r0 = top + (bot - top) * yw;
            top = tl.y + (tr.y - tl.y) * xw;  bot = bl.y + (br.y - bl.y) * xw;  r1 = top + (bot - top) * yw;
            if (!ok) { r0 = 0.0f; r1 = 0.0f; }
            vmax.x = fmaxf(vmax.x, r0);
            vmax.y = fmaxf(vmax.y, r1);
        }
    }

    // output goes to the ORIGINAL roi slot; streaming store (never re-read)
    stcs_f2((float2*)out + (roi * 49 + pix) * (FEAT_C / 2) + t, vmax);
}

extern "C" void kernel_launch(void* const* d_in, const int* in_sizes, int n_in,
                              void* d_out, int out_size)
{
    const float* in      = (const float*)d_in[0];
    const float* rois    = (const float*)d_in[1];
    const float* im_info = (const float*)d_in[2];
    float* out           = (float*)d_out;

    const int N = in_sizes[1] / 5;   // 1024
    bin_rois_kernel<<<1, 1024>>>(rois, N);
    roipool_kernel<<<N * POOL * POOL, 128>>>(in, rois, im_info, out);
}

// round 4
// speedup vs baseline: 1.2876x; 1.2876x over previous
#include <cuda_runtime.h>
#include <cstdint>

// inputs: (B=8, H=160, W=160, C=256) fp32 NHWC
// rois:   (N=1024, 5) fp32 [img_id, x0, y0, x1, y1]
// im_info:(N, 2) fp32 [H_img, W_img]
// output: (N, 7, 7, 256) fp32 = crop_and_resize(14x14 bilinear) -> maxpool 2x2 s2
//
// R4: one block per (roi, pooled-row). 128 threads = 2 pixel-slots x 64 float4
// lanes. ROI/y math amortized over 7 pixels; 16 LDG.128 fully batched per pixel.

#define FEAT_H 160
#define FEAT_W 160
#define FEAT_C 256
#define CROP   14
#define POOL   7
#define C4     (FEAT_C / 4)   // 64 float4 per spatial cell

__device__ __forceinline__ void stcs_f4(float4* p, float4 v) {
    asm volatile("st.global.cs.v4.f32 [%0], {%1, %2, %3, %4};"
                 :: "l"(p), "f"(v.x), "f"(v.y), "f"(v.z), "f"(v.w) : "memory");
}

__global__ __launch_bounds__(128)
void roipool_kernel(const float* __restrict__ in,
                    const float* __restrict__ rois,
                    const float* __restrict__ im_info,
                    float* __restrict__ out)
{
    const int blk  = blockIdx.x;          // roi * 7 + py
    const int roi  = blk / POOL;
    const int py   = blk - roi * POOL;
    const int t    = threadIdx.x;
    const int slot = t >> 6;              // 0 or 1 (warp-pair granular)
    const int lane = t & 63;              // float4 channel lane

    // --- ROI parameters (warp-uniform broadcast loads) ---
    const float b_f   = __ldg(&rois[roi * 5 + 0]);
    const float H_img = __ldg(&im_info[roi * 2 + 0]);
    const float W_img = __ldg(&im_info[roi * 2 + 1]);
    const float x1 = __ldg(&rois[roi * 5 + 1]) / W_img;
    const float y1 = __ldg(&rois[roi * 5 + 2]) / H_img;
    const float x2 = __ldg(&rois[roi * 5 + 3]) / W_img;
    const float y2 = __ldg(&rois[roi * 5 + 4]) / H_img;
    const int   b  = (int)b_f;

    // Reference arithmetic: y1*(Hf-1) + iy * ((y2-y1)*(Hf-1)/(ch-1))
    const float Hm1 = (float)(FEAT_H - 1);
    const float Wm1 = (float)(FEAT_W - 1);
    const float sy = (y2 - y1) * Hm1 / (float)(CROP - 1);
    const float sx = (x2 - x1) * Wm1 / (float)(CROP - 1);
    const float by = y1 * Hm1;
    const float bx = x1 * Wm1;

    // --- the 2 crop-y rows for this pooled row (shared by all 7 pixels) ---
    float ylp[2];
    int   rl[2], rh[2];
    bool  vy[2];
    const int rb = b * (FEAT_H * FEAT_W);
    #pragma unroll
    for (int i = 0; i < 2; ++i) {
        const float y = by + (float)(2 * py + i) * sy;
        vy[i]  = (y >= 0.0f) && (y <= Hm1);
        const float yf = floorf(y);
        ylp[i] = y - yf;
        const int yl = min(max((int)yf, 0), FEAT_H - 1);
        const int yh = min(max((int)yf + 1, 0), FEAT_H - 1);
        rl[i] = (rb + yl * FEAT_W) * C4;     // float4 row offsets
        rh[i] = (rb + yh * FEAT_W) * C4;
    }

    const float4* __restrict__ base = (const float4*)in + lane;
    const float NEG_INF = __int_as_float(0xff800000);

    #pragma unroll
    for (int it = 0; it < 4; ++it) {
        const int px = 2 * it + slot;      // slot1@it3 -> px=7 (skip, warp-granular)
        if (px < POOL) {
            // --- 2 crop-x columns for this pooled pixel ---
            float xlp[2];
            int   cxl[2], cxh[2];
            bool  vx[2];
            #pragma unroll
            for (int i = 0; i < 2; ++i) {
                const float x = bx + (float)(2 * px + i) * sx;
                vx[i]  = (x >= 0.0f) && (x <= Wm1);
                const float xf = floorf(x);
                xlp[i] = x - xf;
                cxl[i] = min(max((int)xf, 0), FEAT_W - 1) * C4;
                cxh[i] = min(max((int)xf + 1, 0), FEAT_W - 1) * C4;
            }

            // --- all 16 taps batched (LDG.128), one latency exposure ---
            float4 v[16];
            #pragma unroll
            for (int iy = 0; iy < 2; ++iy) {
                #pragma unroll
                for (int ix = 0; ix < 2; ++ix) {
                    const int k = (iy * 2 + ix) * 4;
                    v[k + 0] = __ldg(base + (rl[iy] + cxl[ix]));  // tl
                    v[k + 1] = __ldg(base + (rl[iy] + cxh[ix]));  // tr
                    v[k + 2] = __ldg(base + (rh[iy] + cxl[ix]));  // bl
                    v[k + 3] = __ldg(base + (rh[iy] + cxh[ix]));  // br
                }
            }

            // --- bilinear + mask + running max ---
            float4 vmax = make_float4(NEG_INF, NEG_INF, NEG_INF, NEG_INF);
            #pragma unroll
            for (int iy = 0; iy < 2; ++iy) {
                #pragma unroll
                for (int ix = 0; ix < 2; ++ix) {
                    const int k = (iy * 2 + ix) * 4;
                    const float yw = ylp[iy];
                    const float xw = xlp[ix];
                    const bool  ok = vy[iy] && vx[ix];
                    const float4 tl = v[k + 0], tr = v[k + 1];
                    const float4 bl = v[k + 2], br = v[k + 3];
                    float top, bot, r;
                    float4 rv;
                    top = tl.x + (tr.x - tl.x) * xw; bot = bl.x + (br.x - bl.x) * xw; r = top + (bot - top) * yw; rv.x = r;
                    top = tl.y + (tr.y - tl.y) * xw; bot = bl.y + (br.y - bl.y) * xw; r = top + (bot - top) * yw; rv.y = r;
                    top = tl.z + (tr.z - tl.z) * xw; bot = bl.z + (br.z - bl.z) * xw; r = top + (bot - top) * yw; rv.z = r;
                    top = tl.w + (tr.w - tl.w) * xw; bot = bl.w + (br.w - bl.w) * xw; r = top + (bot - top) * yw; rv.w = r;
                    if (!ok) rv = make_float4(0.0f, 0.0f, 0.0f, 0.0f);
                    vmax.x = fmaxf(vmax.x, rv.x);
                    vmax.y = fmaxf(vmax.y, rv.y);
                    vmax.z = fmaxf(vmax.z, rv.z);
                    vmax.w = fmaxf(vmax.w, rv.w);
                }
            }

            stcs_f4((float4*)out + ((roi * 49 + py * POOL + px) * C4 + lane), vmax);
        }
    }
}

extern "C" void kernel_launch(void* const* d_in, const int* in_sizes, int n_in,
                              void* d_out, int out_size)
{
    const float* in      = (const float*)d_in[0];
    const float* rois    = (const float*)d_in[1];
    const float* im_info = (const float*)d_in[2];
    float* out           = (float*)d_out;

    const int N = in_sizes[1] / 5;   // 1024
    roipool_kernel<<<N * POOL, 128>>>(in, rois, im_info, out);
}

// round 5
// speedup vs baseline: 1.4406x; 1.1188x over previous
#include <cuda_runtime.h>
#include <cstdint>

// inputs: (B=8, H=160, W=160, C=256) fp32 NHWC
// rois:   (N=1024, 5) fp32 [img_id, x0, y0, x1, y1]
// im_info:(N, 2) fp32 [H_img, W_img]
// output: (N, 7, 7, 256) fp32 = crop_and_resize(14x14 bilinear) -> maxpool 2x2 s2
//
// R5: R4 row-block structure (one block per (roi, pooled-row), 2 pixel-slots x
// 64 float4 lanes) + image-id-binned ROI execution order for L2 locality.

#define FEAT_H 160
#define FEAT_W 160
#define FEAT_C 256
#define CROP   14
#define POOL   7
#define C4     (FEAT_C / 4)   // 64 float4 per spatial cell
#define NBATCH 8
#define MAXROI 4096

__device__ int g_order[MAXROI];

// ---- single-block binning kernel: sort roi indices by image id ----
__global__ void bin_rois_kernel(const float* __restrict__ rois, int n)
{
    __shared__ int s_cnt[NBATCH];
    __shared__ int s_cur[NBATCH];
    const int t = threadIdx.x;

    if (t < NBATCH) s_cnt[t] = 0;
    __syncthreads();

    int bin = -1;
    if (t < n) {
        bin = (int)rois[t * 5 + 0];
        bin = min(max(bin, 0), NBATCH - 1);
        atomicAdd(&s_cnt[bin], 1);
    }
    __syncthreads();

    if (t == 0) {
        int acc = 0;
        #pragma unroll
        for (int i = 0; i < NBATCH; ++i) { s_cur[i] = acc; acc += s_cnt[i]; }
    }
    __syncthreads();

    if (t < n) {
        int pos = atomicAdd(&s_cur[bin], 1);
        g_order[pos] = t;
    }
}

__device__ __forceinline__ void stcs_f4(float4* p, float4 v) {
    asm volatile("st.global.cs.v4.f32 [%0], {%1, %2, %3, %4};"
                 :: "l"(p), "f"(v.x), "f"(v.y), "f"(v.z), "f"(v.w) : "memory");
}

__global__ __launch_bounds__(128)
void roipool_kernel(const float* __restrict__ in,
                    const float* __restrict__ rois,
                    const float* __restrict__ im_info,
                    float* __restrict__ out)
{
    const int blk  = blockIdx.x;          // sorted_roi * 7 + py
    const int sroi = blk / POOL;
    const int py   = blk - sroi * POOL;
    const int roi  = g_order[sroi];       // image-binned roi index (broadcast)
    const int t    = threadIdx.x;
    const int slot = t >> 6;              // 0 or 1 (warp-pair granular)
    const int lane = t & 63;              // float4 channel lane

    // --- ROI parameters (warp-uniform broadcast loads) ---
    const float b_f   = __ldg(&rois[roi * 5 + 0]);
    const float H_img = __ldg(&im_info[roi * 2 + 0]);
    const float W_img = __ldg(&im_info[roi * 2 + 1]);
    const float x1 = __ldg(&rois[roi * 5 + 1]) / W_img;
    const float y1 = __ldg(&rois[roi * 5 + 2]) / H_img;
    const float x2 = __ldg(&rois[roi * 5 + 3]) / W_img;
    const float y2 = __ldg(&rois[roi * 5 + 4]) / H_img;
    const int   b  = (int)b_f;

    // Reference arithmetic: y1*(Hf-1) + iy * ((y2-y1)*(Hf-1)/(ch-1))
    const float Hm1 = (float)(FEAT_H - 1);
    const float Wm1 = (float)(FEAT_W - 1);
    const float sy = (y2 - y1) * Hm1 / (float)(CROP - 1);
    const float sx = (x2 - x1) * Wm1 / (float)(CROP - 1);
    const float by = y1 * Hm1;
    const float bx = x1 * Wm1;

    // --- the 2 crop-y rows for this pooled row (shared by all 7 pixels) ---
    float ylp[2];
    int   rl[2], rh[2];
    bool  vy[2];
    const int rb = b * (FEAT_H * FEAT_W);
    #pragma unroll
    for (int i = 0; i < 2; ++i) {
        const float y = by + (float)(2 * py + i) * sy;
        vy[i]  = (y >= 0.0f) && (y <= Hm1);
        const float yf = floorf(y);
        ylp[i] = y - yf;
        const int yl = min(max((int)yf, 0), FEAT_H - 1);
        const int yh = min(max((int)yf + 1, 0), FEAT_H - 1);
        rl[i] = (rb + yl * FEAT_W) * C4;     // float4 row offsets
        rh[i] = (rb + yh * FEAT_W) * C4;
    }

    const float4* __restrict__ base = (const float4*)in + lane;
    const float NEG_INF = __int_as_float(0xff800000);

    #pragma unroll
    for (int it = 0; it < 4; ++it) {
        const int px = 2 * it + slot;      // slot1@it3 -> px=7 (skip, warp-granular)
        if (px < POOL) {
            // --- 2 crop-x columns for this pooled pixel ---
            float xlp[2];
            int   cxl[2], cxh[2];
            bool  vx[2];
            #pragma unroll
            for (int i = 0; i < 2; ++i) {
                const float x = bx + (float)(2 * px + i) * sx;
                vx[i]  = (x >= 0.0f) && (x <= Wm1);
                const float xf = floorf(x);
                xlp[i] = x - xf;
                cxl[i] = min(max((int)xf, 0), FEAT_W - 1) * C4;
                cxh[i] = min(max((int)xf + 1, 0), FEAT_W - 1) * C4;
            }

            // --- all 16 taps batched (LDG.128), one latency exposure ---
            float4 v[16];
            #pragma unroll
            for (int iy = 0; iy < 2; ++iy) {
                #pragma unroll
                for (int ix = 0; ix < 2; ++ix) {
                    const int k = (iy * 2 + ix) * 4;
                    v[k + 0] = __ldg(base + (rl[iy] + cxl[ix]));  // tl
                    v[k + 1] = __ldg(base + (rl[iy] + cxh[ix]));  // tr
                    v[k + 2] = __ldg(base + (rh[iy] + cxl[ix]));  // bl
                    v[k + 3] = __ldg(base + (rh[iy] + cxh[ix]));  // br
                }
            }

            // --- bilinear + mask + running max ---
            float4 vmax = make_float4(NEG_INF, NEG_INF, NEG_INF, NEG_INF);
            #pragma unroll
            for (int iy = 0; iy < 2; ++iy) {
                #pragma unroll
                for (int ix = 0; ix < 2; ++ix) {
                    const int k = (iy * 2 + ix) * 4;
                    const float yw = ylp[iy];
                    const float xw = xlp[ix];
                    const bool  ok = vy[iy] && vx[ix];
                    const float4 tl = v[k + 0], tr = v[k + 1];
                    const float4 bl = v[k + 2], br = v[k + 3];
                    float top, bot, r;
                    float4 rv;
                    top = tl.x + (tr.x - tl.x) * xw; bot = bl.x + (br.x - bl.x) * xw; r = top + (bot - top) * yw; rv.x = r;
                    top = tl.y + (tr.y - tl.y) * xw; bot = bl.y + (br.y - bl.y) * xw; r = top + (bot - top) * yw; rv.y = r;
                    top = tl.z + (tr.z - tl.z) * xw; bot = bl.z + (br.z - bl.z) * xw; r = top + (bot - top) * yw; rv.z = r;
                    top = tl.w + (tr.w - tl.w) * xw; bot = bl.w + (br.w - bl.w) * xw; r = top + (bot - top) * yw; rv.w = r;
                    if (!ok) rv = make_float4(0.0f, 0.0f, 0.0f, 0.0f);
                    vmax.x = fmaxf(vmax.x, rv.x);
                    vmax.y = fmaxf(vmax.y, rv.y);
                    vmax.z = fmaxf(vmax.z, rv.z);
                    vmax.w = fmaxf(vmax.w, rv.w);
                }
            }

            // output goes to the ORIGINAL roi slot; streaming store (never re-read)
            stcs_f4((float4*)out + ((roi * 49 + py * POOL + px) * C4 + lane), vmax);
        }
    }
}

extern "C" void kernel_launch(void* const* d_in, const int* in_sizes, int n_in,
                              void* d_out, int out_size)
{
    const float* in      = (const float*)d_in[0];
    const float* rois    = (const float*)d_in[1];
    const float* im_info = (const float*)d_in[2];
    float* out           = (float*)d_out;

    const int N = in_sizes[1] / 5;   // 1024
    bin_rois_kernel<<<1, 1024>>>(rois, N);
    roipool_kernel<<<N * POOL, 128>>>(in, rois, im_info, out);
}